// round 11
// baseline (speedup 1.0000x reference)
#include <cuda_runtime.h>
#include <cstdint>

#define NB 25
#define NT 40

// Scratch (static device arrays — allocation-free per harness rules)
__device__ float g_buf1[1000 * 8 * 32 * 32];   // stage A pooled spikes [bt][8][32][32]
__device__ float g_buf2[1000 * 16 * 8 * 8];    // stage B pooled spikes [bt][1024]
__device__ float g_zpart[1000 * 4 * 64];       // fc1 partials [bt][ks][64]

__device__ __forceinline__ void cp16(uint32_t dst, const void* src, int bytes) {
    asm volatile("cp.async.cg.shared.global [%0], [%1], 16, %2;\n"
                 :: "r"(dst), "l"(src), "r"(bytes));
}
__device__ __forceinline__ void cp_commit() { asm volatile("cp.async.commit_group;\n" ::); }
__device__ __forceinline__ void cp_wait2()  { asm volatile("cp.async.wait_group 2;\n" ::); }
__device__ __forceinline__ void cp_wait4()  { asm volatile("cp.async.wait_group 4;\n" ::); }
__device__ __forceinline__ uint32_t saddr(const void* p) {
    return (uint32_t)__cvta_generic_to_shared(p);
}

// ---- packed f32x2 helpers (sm_103a) ---------------------------------------
__device__ __forceinline__ unsigned long long bcast2(float x) {
    unsigned long long r;
    asm("mov.b64 %0, {%1, %1};" : "=l"(r) : "f"(x));
    return r;
}
__device__ __forceinline__ void fma2(unsigned long long& d,
                                     unsigned long long a, unsigned long long b) {
    asm("fma.rn.f32x2 %0, %1, %2, %0;" : "+l"(d) : "l"(a), "l"(b));
}
__device__ __forceinline__ void unpk2(unsigned long long v, float& lo, float& hi) {
    asm("mov.b64 {%0, %1}, %2;" : "=f"(lo), "=f"(hi) : "l"(v));
}

// ---------------------------------------------------------------------------
// Stage A: conv1 (2->8, 3x3, s2, p1) + IAF over T + 2x2 avgpool, fused.
// grid = (16 row-tiles, 25 b), block = 256, 3 CTAs/SM (single wave: 400<444).
// Thread = 2 horizontal px x 4 oc (2 f32x2 oc-pairs). Weights live in SMEM
// as packed f32x2 pairs (3 broadcast LDS.128 per (ic,kh)) -> ~65 regs/thread.
// RING-6 cp.async pipeline, 2 t-steps per barrier pair.
// Dyn smem (floats): sw[144]@0, wpk[144]@144 (72 x f32x2), spool[1024]@288,
// sx[6][2][9][132]@1312. Row layout: zero pad at [3], data at [4+iw].
// ---------------------------------------------------------------------------
#define KA_SMEM_FLOATS (1312 + 6 * 2 * 9 * 132)
__global__ __launch_bounds__(256, 3) void kA(const float* __restrict__ x,
                                             const float* __restrict__ w1) {
    extern __shared__ float smA[];
    float* sw    = smA;                 // [144]
    float* wpk   = smA + 144;           // [72 u64] packed weight pairs
    float* spool = smA + 288;           // [2][8][2][32]
    float* sxp   = smA + 1312;          // [6][2][9][132]

    const int tr = blockIdx.x;   // output rows [4*tr, 4*tr+4)
    const int b  = blockIdx.y;
    const int tid = threadIdx.x;

    if (tid < 144) sw[tid] = w1[tid];
    // packed weights (read w1 from global directly; no barrier needed):
    // u64 entry e = r*2+p, r = og*18 + ic*9 + kh*3 + kw; pair covers
    // oc = og*4+2p (lo) and og*4+2p+1 (hi)
    if (tid < 72) {
        int p  = tid & 1;
        int r  = tid >> 1;                 // 0..35
        int kw = r % 3, kh = (r / 3) % 3, ic = (r / 9) % 2, ogg = r / 18;
        int oclo = ogg * 4 + 2 * p;
        wpk[tid * 2]     = w1[((oclo)     * 2 + ic) * 9 + kh * 3 + kw];
        wpk[tid * 2 + 1] = w1[((oclo + 1) * 2 + ic) * 9 + kh * 3 + kw];
    }
    // zero pads sx[bu][ic][r][3] for all 6 buffers (6*18 = 108 slots)
    if (tid >= 144 && tid < 252) {
        int i = tid - 144;
        int bu = i / 18, r = i % 18;
        sxp[((bu * 2 + r / 9) * 9 + (r % 9)) * 132 + 3] = 0.f;
    }

    // tid bits: [0:3]=pcl, [4]=rowlsb, [5]=pch, [6]=rowhi, [7]=og
    const int pcl    = tid & 15;
    const int rowlsb = (tid >> 4) & 1;
    const int pch    = (tid >> 5) & 1;
    const int rowhi  = (tid >> 6) & 1;
    const int og     = (tid >> 7) & 1;
    const int pc  = pcl + 16 * pch;      // pool col 0..31 (= pair ow 2pc,2pc+1)
    const int row = rowlsb + 2 * rowhi;  // local output row 0..3
    const int ihb = 8 * tr - 1;

    // load slots: 2ch x 9row x 32 float4 = 576 over 256 threads
    int sch[3], sr[3], sc[3], sih[3]; bool sact[3];
#pragma unroll
    for (int k = 0; k < 3; k++) {
        int i = tid + k * 256;
        sact[k] = (i < 576);
        int ii = sact[k] ? i : 0;
        sch[k] = (ii >= 288) ? 1 : 0;
        int rem = ii - sch[k] * 288;
        sr[k] = rem >> 5; sc[k] = rem & 31; sih[k] = ihb + sr[k];
    }

    auto issue = [&](int t, int bu) {
        const float* xp = x + (size_t)(b * NT + t) * 32768;
#pragma unroll
        for (int k = 0; k < 3; k++) {
            if (!sact[k]) continue;
            int ih = (sih[k] < 0) ? 0 : sih[k];
            int by = ((unsigned)sih[k] < 128u) ? 16 : 0;
            cp16(saddr(&sxp[((bu * 2 + sch[k]) * 9 + sr[k]) * 132 + 4 + sc[k] * 4]),
                 xp + (sch[k] * 128 + ih) * 128 + sc[k] * 4, by);
        }
    };

    // prologue: 4 tiles in flight
    issue(0, 0); cp_commit();
    issue(1, 1); cp_commit();
    issue(2, 2); cp_commit();
    issue(3, 3); cp_commit();
    __syncthreads();   // sw + wpk + pads visible

    const ulonglong2* wpk2 = (const ulonglong2*)wpk;  // 16B aligned (offset 576B)

    float v[2][4];
#pragma unroll
    for (int px = 0; px < 2; px++)
#pragma unroll
      for (int i = 0; i < 4; i++) v[px][i] = 0.f;

    auto compute = [&](int bu, int sb) {
        unsigned long long a00 = 0ull, a01 = 0ull, a10 = 0ull, a11 = 0ull;
#pragma unroll
        for (int ic = 0; ic < 2; ic++)
#pragma unroll
          for (int kh = 0; kh < 3; kh++) {
            const float* rp = &sxp[((bu * 2 + ic) * 9 + 2 * row + kh) * 132];
            float  xm = rp[3 + 4 * pc];
            float4 r4 = *(const float4*)&rp[4 + 4 * pc];
            const ulonglong2* wk = wpk2 + og * 18 + ic * 9 + kh * 3;
            ulonglong2 w0 = wk[0], w1v = wk[1], w2v = wk[2];
            unsigned long long X;
            X = bcast2(xm);                       // px0 kw0
            fma2(a00, X, w0.x);  fma2(a01, X, w0.y);
            X = bcast2(r4.x);                     // px0 kw1
            fma2(a00, X, w1v.x); fma2(a01, X, w1v.y);
            X = bcast2(r4.y);                     // px0 kw2 + px1 kw0 (shared)
            fma2(a00, X, w2v.x); fma2(a01, X, w2v.y);
            fma2(a10, X, w0.x);  fma2(a11, X, w0.y);
            X = bcast2(r4.z);                     // px1 kw1
            fma2(a10, X, w1v.x); fma2(a11, X, w1v.y);
            X = bcast2(r4.w);                     // px1 kw2
            fma2(a10, X, w2v.x); fma2(a11, X, w2v.y);
          }
        // unpack -> IAF + pool (horizontal pair in-thread, vertical via shfl)
        float acc[2][4];
        unpk2(a00, acc[0][0], acc[0][1]);
        unpk2(a01, acc[0][2], acc[0][3]);
        unpk2(a10, acc[1][0], acc[1][1]);
        unpk2(a11, acc[1][2], acc[1][3]);
#pragma unroll
        for (int i = 0; i < 4; i++) {
            float h = 0.f;
#pragma unroll
            for (int px = 0; px < 2; px++) {
                float vv = v[px][i] + acc[px][i];
                float s  = (vv >= 1.0f) ? 1.0f : 0.0f;
                vv = (s != 0.f) ? 0.f : vv;
                v[px][i] = fmaxf(vv, -1.0f);
                h += s;
            }
            h += __shfl_xor_sync(0xffffffffu, h, 16);
            if (rowlsb == 0)
                spool[((sb * 8 + og * 4 + i) * 2 + rowhi) * 32 + pc] = h * 0.25f;
        }
    };

    for (int t = 0; t < NT; t += 2) {
        if (t + 4 < NT) issue(t + 4, (t + 4) % 6);
        cp_commit();
        if (t + 5 < NT) issue(t + 5, (t + 5) % 6);
        cp_commit();
        cp_wait4();          // tiles t, t+1 complete (this thread)
        __syncthreads();     // visible to all; spool reusable

        compute(t % 6, 0);
        compute((t + 1) % 6, 1);
        __syncthreads();

        // pooled stores: 2 steps x 512 values, coalesced
#pragma unroll
        for (int sb = 0; sb < 2; sb++) {
            float* outp = g_buf1 + (size_t)(b * NT + t + sb) * 8192;
#pragma unroll
            for (int k = 0; k < 2; k++) {
                int i = tid + k * 256;
                int oc = i >> 6, prow = (i >> 5) & 1, pcc = i & 31;
                outp[oc * 1024 + (2 * tr + prow) * 32 + pcc] =
                    spool[((sb * 8 + oc) * 2 + prow) * 32 + pcc];
            }
        }
    }
}

// ---------------------------------------------------------------------------
// Stage B: conv2 (8->16, 3x3, s2, p1) + IAF + 2x2 avgpool, fused.
// grid = (4 row-tiles, 4 oc-splits, 25 b) = 400 CTAs, block = 128, 4 CTAs/SM.
// Thread = 2 horizontal px x 1 oc; 4 oc per CTA (72 weight regs).
// RING-4 cp.async, distance 2, 2 t-steps per barrier pair.
// Dyn smem (floats): sw[288]@0, spool[128]@288, sx[4][8][9][36]@416.
// ---------------------------------------------------------------------------
#define KB_SMEM_FLOATS (416 + 4 * 8 * 9 * 36)
__global__ __launch_bounds__(128, 4) void kB(const float* __restrict__ w2) {
    extern __shared__ float smB[];
    float* sw    = smB;            // [288] = 4 oc x 72
    float* spool = smB + 288;      // [2][4][2][8]
    float* sxp   = smB + 416;      // [4][8][9][36]

    const int tr = blockIdx.x;   // out rows [4*tr, 4*tr+4)
    const int os = blockIdx.y;   // oc base = 4*os
    const int b  = blockIdx.z;
    const int tid = threadIdx.x;

    for (int i = tid; i < 288; i += 128) sw[i] = w2[os * 288 + i];
    for (int i = tid; i < 288; i += 128) {      // pads: 4 bufs x 72 rows
        int bu = i / 72, r = i % 72;
        sxp[((bu * 8 + r / 9) * 9 + (r % 9)) * 36 + 3] = 0.f;
    }

    // tid bits: [0:2]=pc, [3]=rowlsb, [4:5]=ocl, [6]=rowhi
    const int pc     = tid & 7;
    const int rowlsb = (tid >> 3) & 1;
    const int ocl    = (tid >> 4) & 3;
    const int rowhi  = (tid >> 6) & 1;
    const int row    = rowlsb + 2 * rowhi;
    const int ihb = 8 * tr - 1;

    // load slots: 8ch x 9row x 8 float4 = 576 over 128 thr -> 4 full + 1 partial
    int lch[5], lr[5], lc[5], lih[5]; bool lact[5];
#pragma unroll
    for (int k = 0; k < 5; k++) {
        int i = tid + k * 128;
        lact[k] = (i < 576);
        int ii = lact[k] ? i : 0;
        lch[k] = ii / 72; int rem = ii - lch[k] * 72;
        lr[k] = rem >> 3; lc[k] = rem & 7; lih[k] = ihb + lr[k];
    }

    auto issue = [&](int t, int bu) {
        const float* inp = g_buf1 + (size_t)(b * NT + t) * 8192;
#pragma unroll
        for (int k = 0; k < 5; k++) {
            if (!lact[k]) continue;
            int ih = (lih[k] < 0) ? 0 : lih[k];
            int by = ((unsigned)lih[k] < 32u) ? 16 : 0;
            cp16(saddr(&sxp[((bu * 8 + lch[k]) * 9 + lr[k]) * 36 + 4 + lc[k] * 4]),
                 inp + (lch[k] * 32 + ih) * 32 + lc[k] * 4, by);
        }
    };

    issue(0, 0); cp_commit();
    issue(1, 1); cp_commit();
    __syncthreads();

    // weights: 1 oc per thread (oc = os*4 + ocl); sw row = 72 floats
    float wrg[8][3][3];
#pragma unroll
    for (int ic = 0; ic < 8; ic++)
#pragma unroll
      for (int kh = 0; kh < 3; kh++)
#pragma unroll
        for (int kw = 0; kw < 3; kw++)
            wrg[ic][kh][kw] = sw[ocl * 72 + ic * 9 + kh * 3 + kw];

    float v[2];
    v[0] = v[1] = 0.f;

    auto compute = [&](int bu, int sb) {
        float acc0 = 0.f, acc1 = 0.f;
#pragma unroll
        for (int ic = 0; ic < 8; ic++)
#pragma unroll
          for (int kh = 0; kh < 3; kh++) {
            const float* rp = &sxp[((bu * 8 + ic) * 9 + 2 * row + kh) * 36];
            float  xm = rp[3 + 4 * pc];
            float4 r4 = *(const float4*)&rp[4 + 4 * pc];
            float w0 = wrg[ic][kh][0], w1r = wrg[ic][kh][1], w2r = wrg[ic][kh][2];
            acc0 = fmaf(xm,   w0,  acc0);
            acc0 = fmaf(r4.x, w1r, acc0);
            acc0 = fmaf(r4.y, w2r, acc0);
            acc1 = fmaf(r4.y, w0,  acc1);
            acc1 = fmaf(r4.z, w1r, acc1);
            acc1 = fmaf(r4.w, w2r, acc1);
          }
        float h;
        {
            float vv = v[0] + acc0;
            float s  = (vv >= 1.0f) ? 1.0f : 0.0f;
            vv = (s != 0.f) ? 0.f : vv;
            v[0] = fmaxf(vv, -1.0f);
            h = s;
        }
        {
            float vv = v[1] + acc1;
            float s  = (vv >= 1.0f) ? 1.0f : 0.0f;
            vv = (s != 0.f) ? 0.f : vv;
            v[1] = fmaxf(vv, -1.0f);
            h += s;
        }
        h += __shfl_xor_sync(0xffffffffu, h, 8);   // vertical pair (rowlsb)
        if (rowlsb == 0)
            spool[((sb * 4 + ocl) * 2 + rowhi) * 8 + pc] = h * 0.25f;
    };

    for (int t = 0; t < NT; t += 2) {
        if (t + 2 < NT) issue(t + 2, (t + 2) & 3);
        cp_commit();
        if (t + 3 < NT) issue(t + 3, (t + 3) & 3);
        cp_commit();
        cp_wait2();
        __syncthreads();

        compute(t & 3, 0);
        compute((t + 1) & 3, 1);
        __syncthreads();

        if (tid < 64) {
            int oc2 = tid >> 4, prow = (tid >> 3) & 1, pcc = tid & 7;
#pragma unroll
            for (int sb = 0; sb < 2; sb++) {
                g_buf2[(size_t)(b * NT + t + sb) * 1024 + (os * 4 + oc2) * 64 +
                       (2 * tr + prow) * 8 + pcc] =
                    spool[((sb * 4 + oc2) * 2 + prow) * 8 + pcc];
            }
        }
    }
}

// ---------------------------------------------------------------------------
// Stage C1: fc1 partial GEMM  z[bt,64] = buf2[bt,1024] @ w3^T, k-split x4.
// grid = (32 bt-tiles of 32 rows, 4 k-splits), block 256, thread tile 2x4.
// zpart layout: [bt][ks][64] (contiguous per bt for kC2).
// ---------------------------------------------------------------------------
__global__ __launch_bounds__(256) void kC1(const float* __restrict__ w3) {
    const int bt0 = blockIdx.x * 32;
    const int ks  = blockIdx.y;
    const int tid = threadIdx.x;
    __shared__ float xs[32][64];
    __shared__ float ws[64][65];
    const int rp = tid >> 4, oq = tid & 15;

    float acc[2][4];
#pragma unroll
    for (int r = 0; r < 2; r++)
#pragma unroll
      for (int j = 0; j < 4; j++) acc[r][j] = 0.f;

    for (int kc = 0; kc < 4; kc++) {
        int koff = ks * 256 + kc * 64;
        __syncthreads();
        for (int i = tid; i < 512; i += 256) {
            int r = i >> 4, c4 = i & 15;
            int bt = bt0 + r;
            float4 vv = make_float4(0.f, 0.f, 0.f, 0.f);
            if (bt < 1000) vv = *(const float4*)(g_buf2 + (size_t)bt * 1024 + koff + c4 * 4);
            *(float4*)&xs[r][c4 * 4] = vv;
        }
        for (int i = tid; i < 4096; i += 256) {   // transpose w3 chunk into smem
            int o = i >> 6, k = i & 63;
            ws[k][o] = w3[o * 1024 + koff + k];
        }
        __syncthreads();
#pragma unroll 16
        for (int k = 0; k < 64; k++) {
            float a0 = xs[2 * rp][k], a1 = xs[2 * rp + 1][k];
#pragma unroll
            for (int j = 0; j < 4; j++) {
                float wv = ws[k][oq + 16 * j];
                acc[0][j] = fmaf(a0, wv, acc[0][j]);
                acc[1][j] = fmaf(a1, wv, acc[1][j]);
            }
        }
    }
#pragma unroll
    for (int r = 0; r < 2; r++) {
        int bt = bt0 + 2 * rp + r;
        if (bt < 1000) {
#pragma unroll
            for (int j = 0; j < 4; j++)
                g_zpart[((size_t)bt * 4 + ks) * 64 + oq + 16 * j] = acc[r][j];
        }
    }
}

// ---------------------------------------------------------------------------
// Stage C2: contiguous gather + barrier-free scans (per-cell IAF is
// independent across t). grid = 25 (b), block = 256. 3 barriers total.
// ---------------------------------------------------------------------------
__global__ __launch_bounds__(256) void kC2(const float* __restrict__ w4,
                                           float* __restrict__ out) {
    const int b = blockIdx.x;
    const int tid = threadIdx.x;
    __shared__ float zs[NT * 64];    // z1[t][cell]
    __shared__ float ss[NT * 64];    // spikes1[t][cell]
    __shared__ float z2[NT * 11];    // fc2 pre-activations
    __shared__ float w4s[11 * 65];   // padded

    // contiguous load + k-split reduce: [40][4][64] -> [40][64]
    const float* p0 = g_zpart + (size_t)b * NT * 256;
    for (int i = tid; i < 640; i += 256) {
        int t = i >> 4, c4 = i & 15;
        const float* q = p0 + t * 256 + c4 * 4;
        float4 a = *(const float4*)(q);
        float4 c = *(const float4*)(q + 64);
        float4 d = *(const float4*)(q + 128);
        float4 e = *(const float4*)(q + 192);
        *(float4*)&zs[t * 64 + c4 * 4] =
            make_float4(a.x + c.x + d.x + e.x, a.y + c.y + d.y + e.y,
                        a.z + c.z + d.z + e.z, a.w + c.w + d.w + e.w);
    }
    for (int i = tid; i < 704; i += 256) {
        int o = i >> 6, j = i & 63;
        w4s[o * 65 + j] = w4[i];
    }
    __syncthreads();

    // Phase 1: per-cell IAF scan, barrier-free
    if (tid < 64) {
        float v1 = 0.f;
#pragma unroll 8
        for (int t = 0; t < NT; t++) {
            float vv = v1 + zs[t * 64 + tid];
            float s  = (vv >= 1.0f) ? 1.0f : 0.0f;
            vv = (s != 0.f) ? 0.f : vv;
            v1 = fmaxf(vv, -1.0f);
            ss[t * 64 + tid] = s;
        }
    }
    __syncthreads();

    // Phase 2: z2[t][o] = ss[t][:] . w4[o][:]
    for (int i = tid; i < NT * 11; i += 256) {
        int t = i / 11, o = i - 11 * t;
        const float* sp = &ss[t * 64];
        const float* wp = &w4s[o * 65];
        float za = 0.f, zb = 0.f, zc = 0.f, zd = 0.f;
#pragma unroll
        for (int j = 0; j < 64; j += 4) {
            za = fmaf(sp[j],     wp[j],     za);
            zb = fmaf(sp[j + 1], wp[j + 1], zb);
            zc = fmaf(sp[j + 2], wp[j + 2], zc);
            zd = fmaf(sp[j + 3], wp[j + 3], zd);
        }
        z2[i] = (za + zb) + (zc + zd);
    }
    __syncthreads();

    // Phase 3: per-output IAF scan, barrier-free
    if (tid < 11) {
        float v2 = 0.f;
#pragma unroll 8
        for (int t = 0; t < NT; t++) {
            float vv2 = v2 + z2[t * 11 + tid];
            float s2  = (vv2 >= 1.0f) ? 1.0f : 0.0f;
            vv2 = (s2 != 0.f) ? 0.f : vv2;
            v2 = fmaxf(vv2, -1.0f);
            out[(b * NT + t) * 11 + tid] = s2;
        }
    }
}

// ---------------------------------------------------------------------------
extern "C" void kernel_launch(void* const* d_in, const int* in_sizes, int n_in,
                              void* d_out, int out_size) {
    (void)in_sizes; (void)n_in; (void)out_size;
    const float* x  = (const float*)d_in[0];
    const float* w1 = (const float*)d_in[1];
    const float* w2 = (const float*)d_in[2];
    const float* w3 = (const float*)d_in[3];
    const float* w4 = (const float*)d_in[4];
    float* out = (float*)d_out;

    const int kaBytes = KA_SMEM_FLOATS * 4;   // ~62.2 KB
    const int kbBytes = KB_SMEM_FLOATS * 4;   // ~43.1 KB
    cudaFuncSetAttribute(kA, cudaFuncAttributeMaxDynamicSharedMemorySize, kaBytes);
    cudaFuncSetAttribute(kB, cudaFuncAttributeMaxDynamicSharedMemorySize, kbBytes);

    kA<<<dim3(16, 25), 256, kaBytes>>>(x, w1);
    kB<<<dim3(4, 4, 25), 128, kbBytes>>>(w2);
    kC1<<<dim3(32, 4), 256>>>(w3);
    kC2<<<25, 256>>>(w4, out);
}

// round 13
// speedup vs baseline: 1.8293x; 1.8293x over previous
#include <cuda_runtime.h>
#include <cstdint>

#define NB 25
#define NT 40

// Scratch (static device arrays — allocation-free per harness rules)
__device__ float g_buf1[1000 * 8 * 32 * 32];   // stage A pooled spikes [bt][8][32][32]
__device__ float g_buf2[1000 * 16 * 8 * 8];    // stage B pooled spikes [bt][1024]
__device__ float g_zpart[1000 * 4 * 64];       // fc1 partials [bt][ks][64]

__device__ __forceinline__ void cp16(uint32_t dst, const void* src, int bytes) {
    asm volatile("cp.async.cg.shared.global [%0], [%1], 16, %2;\n"
                 :: "r"(dst), "l"(src), "r"(bytes));
}
__device__ __forceinline__ void cp_commit() { asm volatile("cp.async.commit_group;\n" ::); }
__device__ __forceinline__ void cp_wait2()  { asm volatile("cp.async.wait_group 2;\n" ::); }
__device__ __forceinline__ uint32_t saddr(const void* p) {
    return (uint32_t)__cvta_generic_to_shared(p);
}

// ---- packed f32x2 helpers (sm_103a) ---------------------------------------
__device__ __forceinline__ unsigned long long pk2(float lo, float hi) {
    unsigned long long r;
    asm("mov.b64 %0, {%1, %2};" : "=l"(r) : "f"(lo), "f"(hi));
    return r;
}
__device__ __forceinline__ unsigned long long bcast2(float x) {
    unsigned long long r;
    asm("mov.b64 %0, {%1, %1};" : "=l"(r) : "f"(x));
    return r;
}
__device__ __forceinline__ void fma2(unsigned long long& d,
                                     unsigned long long a, unsigned long long b) {
    asm("fma.rn.f32x2 %0, %1, %2, %0;" : "+l"(d) : "l"(a), "l"(b));
}
__device__ __forceinline__ void unpk2(unsigned long long v, float& lo, float& hi) {
    asm("mov.b64 {%0, %1}, %2;" : "=f"(lo), "=f"(hi) : "l"(v));
}

// ---------------------------------------------------------------------------
// Stage A: conv1 (2->8, 3x3, s2, p1) + IAF over T + 2x2 avgpool, fused.
// grid = (16 row-tiles, 25 b), block = 256, 2 CTAs/SM.
// Thread = 2 horizontal px x 4 oc (2 f32x2 oc-pairs). 4-buffer cp.async
// ring, 2 t-steps per barrier. Pooled spikes stored DIRECT to gmem from the
// shuffle result (no smem staging, 1 barrier per t-step).
// smem row layout: zero pad at [3], data at [4+iw].
// ---------------------------------------------------------------------------
__global__ __launch_bounds__(256, 2) void kA(const float* __restrict__ x,
                                             const float* __restrict__ w1) {
    const int tr = blockIdx.x;   // output rows [4*tr, 4*tr+4)
    const int b  = blockIdx.y;
    const int tid = threadIdx.x;

    __shared__ float sw[144];
    __shared__ __align__(16) float sx[4][2][9][132]; // [buf][ic][r][4+iw]; [3]=pad

    if (tid < 144) sw[tid] = w1[tid];
    if (tid < 72) { int bu = tid / 18, r = tid % 18; sx[bu][r / 9][r % 9][3] = 0.f; }

    // tid bits: [0:3]=pcl, [4]=rowlsb, [5]=pch, [6]=rowhi, [7]=og
    const int pcl    = tid & 15;
    const int rowlsb = (tid >> 4) & 1;
    const int pch    = (tid >> 5) & 1;
    const int rowhi  = (tid >> 6) & 1;
    const int og     = (tid >> 7) & 1;
    const int pc  = pcl + 16 * pch;      // pool col 0..31 (= pair ow 2pc,2pc+1)
    const int row = rowlsb + 2 * rowhi;  // local output row 0..3
    const int ihb = 8 * tr - 1;

    // load slots: 2ch x 9row x 32 float4 = 576 over 256 threads
    int sch[3], sr[3], sc[3], sih[3]; bool sact[3];
#pragma unroll
    for (int k = 0; k < 3; k++) {
        int i = tid + k * 256;
        sact[k] = (i < 576);
        int ii = sact[k] ? i : 0;
        sch[k] = (ii >= 288) ? 1 : 0;
        int rem = ii - sch[k] * 288;
        sr[k] = rem >> 5; sc[k] = rem & 31; sih[k] = ihb + sr[k];
    }

    auto issue = [&](int t, int bu) {
        const float* xp = x + (size_t)(b * NT + t) * 32768;
#pragma unroll
        for (int k = 0; k < 3; k++) {
            if (!sact[k]) continue;
            int ih = (sih[k] < 0) ? 0 : sih[k];
            int by = ((unsigned)sih[k] < 128u) ? 16 : 0;
            cp16(saddr(&sx[bu][sch[k]][sr[k]][4 + sc[k] * 4]),
                 xp + (sch[k] * 128 + ih) * 128 + sc[k] * 4, by);
        }
    };

    issue(0, 0); cp_commit();
    issue(1, 1); cp_commit();
    __syncthreads();   // sw + pads visible

    // packed weights: wq[ic][kh][kw][p] = {w(oc=og*4+2p), w(oc=og*4+2p+1)}
    unsigned long long wq[2][3][3][2];
#pragma unroll
    for (int ic = 0; ic < 2; ic++)
#pragma unroll
      for (int kh = 0; kh < 3; kh++)
#pragma unroll
        for (int kw = 0; kw < 3; kw++)
#pragma unroll
          for (int p = 0; p < 2; p++) {
            float wlo = sw[(((og * 4 + 2 * p)     * 2 + ic) * 3 + kh) * 3 + kw];
            float whi = sw[(((og * 4 + 2 * p + 1) * 2 + ic) * 3 + kh) * 3 + kw];
            wq[ic][kh][kw][p] = pk2(wlo, whi);
          }

    float v[2][4];
#pragma unroll
    for (int px = 0; px < 2; px++)
#pragma unroll
      for (int i = 0; i < 4; i++) v[px][i] = 0.f;

    // direct-store base: g_buf1[bt][oc][2*tr+rowhi][pc] (oc stride 1024)
    float* const outbase = g_buf1 + (size_t)b * NT * 8192
                         + (og * 4) * 1024 + (2 * tr + rowhi) * 32 + pc;

    auto compute = [&](int bu, int t) {
        unsigned long long a2[2][2];      // [px][pair]
        a2[0][0] = a2[0][1] = a2[1][0] = a2[1][1] = 0ull;
#pragma unroll
        for (int ic = 0; ic < 2; ic++)
#pragma unroll
          for (int kh = 0; kh < 3; kh++) {
            const float* rp = &sx[bu][ic][2 * row + kh][0];
            float  xm = rp[3 + 4 * pc];
            float4 r4 = *(const float4*)&rp[4 + 4 * pc];
            unsigned long long X;
            X = bcast2(xm);                       // px0 kw0
            fma2(a2[0][0], X, wq[ic][kh][0][0]);
            fma2(a2[0][1], X, wq[ic][kh][0][1]);
            X = bcast2(r4.x);                     // px0 kw1
            fma2(a2[0][0], X, wq[ic][kh][1][0]);
            fma2(a2[0][1], X, wq[ic][kh][1][1]);
            X = bcast2(r4.y);                     // px0 kw2 + px1 kw0 (shared)
            fma2(a2[0][0], X, wq[ic][kh][2][0]);
            fma2(a2[0][1], X, wq[ic][kh][2][1]);
            fma2(a2[1][0], X, wq[ic][kh][0][0]);
            fma2(a2[1][1], X, wq[ic][kh][0][1]);
            X = bcast2(r4.z);                     // px1 kw1
            fma2(a2[1][0], X, wq[ic][kh][1][0]);
            fma2(a2[1][1], X, wq[ic][kh][1][1]);
            X = bcast2(r4.w);                     // px1 kw2
            fma2(a2[1][0], X, wq[ic][kh][2][0]);
            fma2(a2[1][1], X, wq[ic][kh][2][1]);
          }
        // unpack -> IAF + pool; direct coalesced store (16 consecutive pc/warp)
        float acc[2][4];
#pragma unroll
        for (int px = 0; px < 2; px++) {
            unpk2(a2[px][0], acc[px][0], acc[px][1]);
            unpk2(a2[px][1], acc[px][2], acc[px][3]);
        }
        float* outp = outbase + (size_t)t * 8192;
#pragma unroll
        for (int i = 0; i < 4; i++) {
            float h = 0.f;
#pragma unroll
            for (int px = 0; px < 2; px++) {
                float vv = v[px][i] + acc[px][i];
                float s  = (vv >= 1.0f) ? 1.0f : 0.0f;
                vv = (s != 0.f) ? 0.f : vv;
                v[px][i] = fmaxf(vv, -1.0f);
                h += s;
            }
            h += __shfl_xor_sync(0xffffffffu, h, 16);   // vertical pair
            if (rowlsb == 0) outp[i * 1024] = h * 0.25f;
        }
    };

    for (int t = 0; t < NT; t += 2) {
        if (t + 2 < NT) issue(t + 2, (t + 2) & 3);
        cp_commit();
        if (t + 3 < NT) issue(t + 3, (t + 3) & 3);
        cp_commit();
        cp_wait2();          // tiles t, t+1 complete (this thread)
        __syncthreads();     // visible to all; prev buffers reusable

        compute(t & 3, t);
        compute((t + 1) & 3, t + 1);
    }
}

// ---------------------------------------------------------------------------
// Stage B: conv2 (8->16, 3x3, s2, p1) + IAF + 2x2 avgpool, fused.
// grid = (4 row-tiles, 2 oc-splits, 25 b), block = 128, 2 CTAs/SM.
// Thread = 2 horizontal px x 2 oc; 8 oc per CTA. 4-buffer ring, 2-step loop,
// direct pooled stores (1 barrier per t-step).
// ---------------------------------------------------------------------------
__global__ __launch_bounds__(128, 2) void kB(const float* __restrict__ w2) {
    const int tr = blockIdx.x;   // out rows [4*tr, 4*tr+4)
    const int os = blockIdx.y;   // oc base = 8*os
    const int b  = blockIdx.z;
    const int tid = threadIdx.x;

    __shared__ float sw[576];
    __shared__ __align__(16) float sx[4][8][9][36]; // [buf][ic][r][4+iw]; [3]=pad

    for (int i = tid; i < 576; i += 128) sw[i] = w2[os * 576 + i];
    for (int i = tid; i < 288; i += 128) {
        int bu = i / 72, r = i % 72;
        sx[bu][r / 9][r % 9][3] = 0.f;
    }

    // tid bits: [0:2]=pc, [3]=rowlsb, [4:5]=ocp, [6]=rowhi
    const int pc     = tid & 7;
    const int rowlsb = (tid >> 3) & 1;
    const int ocp    = (tid >> 4) & 3;
    const int rowhi  = (tid >> 6) & 1;
    const int row    = rowlsb + 2 * rowhi;
    const int ihb = 8 * tr - 1;

    // load slots: 8ch x 9row x 8 float4 = 576 over 128 thr -> 4 full + 1 partial
    int lch[5], lr[5], lc[5], lih[5]; bool lact[5];
#pragma unroll
    for (int k = 0; k < 5; k++) {
        int i = tid + k * 128;
        lact[k] = (i < 576);
        int ii = lact[k] ? i : 0;
        lch[k] = ii / 72; int rem = ii - lch[k] * 72;
        lr[k] = rem >> 3; lc[k] = rem & 7; lih[k] = ihb + lr[k];
    }

    auto issue = [&](int t, int bu) {
        const float* inp = g_buf1 + (size_t)(b * NT + t) * 8192;
#pragma unroll
        for (int k = 0; k < 5; k++) {
            if (!lact[k]) continue;
            int ih = (lih[k] < 0) ? 0 : lih[k];
            int by = ((unsigned)lih[k] < 32u) ? 16 : 0;
            cp16(saddr(&sx[bu][lch[k]][lr[k]][4 + lc[k] * 4]),
                 inp + (lch[k] * 32 + ih) * 32 + lc[k] * 4, by);
        }
    };

    issue(0, 0); cp_commit();
    issue(1, 1); cp_commit();
    __syncthreads();

    // weights: 2 ocs per thread (oc = os*8 + ocp*2 + j); w2 row = 72 floats
    float wrg[8][3][3][2];
#pragma unroll
    for (int ic = 0; ic < 8; ic++)
#pragma unroll
      for (int kh = 0; kh < 3; kh++)
#pragma unroll
        for (int kw = 0; kw < 3; kw++)
#pragma unroll
          for (int j = 0; j < 2; j++)
            wrg[ic][kh][kw][j] = sw[(ocp * 2 + j) * 72 + ic * 9 + kh * 3 + kw];

    float v[2][2];
    v[0][0] = v[0][1] = v[1][0] = v[1][1] = 0.f;

    // direct-store base: g_buf2[bt][os*8+ocp*2+j][(2*tr+rowhi)*8 + pc]
    float* const outbase = g_buf2 + (size_t)b * NT * 1024
                         + (os * 8 + ocp * 2) * 64 + (2 * tr + rowhi) * 8 + pc;

    auto compute = [&](int bu, int t) {
        float acc[2][2];
        acc[0][0] = acc[0][1] = acc[1][0] = acc[1][1] = 0.f;
#pragma unroll
        for (int ic = 0; ic < 8; ic++)
#pragma unroll
          for (int kh = 0; kh < 3; kh++) {
            const float* rp = &sx[bu][ic][2 * row + kh][0];
            float  xm = rp[3 + 4 * pc];
            float4 r4 = *(const float4*)&rp[4 + 4 * pc];
#pragma unroll
            for (int j = 0; j < 2; j++) {
                float w0 = wrg[ic][kh][0][j], w1r = wrg[ic][kh][1][j], w2r = wrg[ic][kh][2][j];
                acc[0][j] = fmaf(xm,   w0,  acc[0][j]);
                acc[0][j] = fmaf(r4.x, w1r, acc[0][j]);
                acc[0][j] = fmaf(r4.y, w2r, acc[0][j]);
                acc[1][j] = fmaf(r4.y, w0,  acc[1][j]);
                acc[1][j] = fmaf(r4.z, w1r, acc[1][j]);
                acc[1][j] = fmaf(r4.w, w2r, acc[1][j]);
            }
          }
        float* outp = outbase + (size_t)t * 1024;
#pragma unroll
        for (int j = 0; j < 2; j++) {
            float h = 0.f;
#pragma unroll
            for (int px = 0; px < 2; px++) {
                float vv = v[px][j] + acc[px][j];
                float s  = (vv >= 1.0f) ? 1.0f : 0.0f;
                vv = (s != 0.f) ? 0.f : vv;
                v[px][j] = fmaxf(vv, -1.0f);
                h += s;
            }
            h += __shfl_xor_sync(0xffffffffu, h, 8);   // vertical pair (rowlsb)
            if (rowlsb == 0) outp[j * 64] = h * 0.25f;
        }
    };

    for (int t = 0; t < NT; t += 2) {
        if (t + 2 < NT) issue(t + 2, (t + 2) & 3);
        cp_commit();
        if (t + 3 < NT) issue(t + 3, (t + 3) & 3);
        cp_commit();
        cp_wait2();
        __syncthreads();

        compute(t & 3, t);
        compute((t + 1) & 3, t + 1);
    }
}

// ---------------------------------------------------------------------------
// Stage C1: fc1 partial GEMM  z[bt,64] = buf2[bt,1024] @ w3^T, k-split x4.
// grid = (32 bt-tiles of 32 rows, 4 k-splits), block 256, thread tile 2x4.
// zpart layout: [bt][ks][64] (contiguous per bt for kC2).
// ---------------------------------------------------------------------------
__global__ __launch_bounds__(256) void kC1(const float* __restrict__ w3) {
    const int bt0 = blockIdx.x * 32;
    const int ks  = blockIdx.y;
    const int tid = threadIdx.x;
    __shared__ float xs[32][64];
    __shared__ float ws[64][65];
    const int rp = tid >> 4, oq = tid & 15;

    float acc[2][4];
#pragma unroll
    for (int r = 0; r < 2; r++)
#pragma unroll
      for (int j = 0; j < 4; j++) acc[r][j] = 0.f;

    for (int kc = 0; kc < 4; kc++) {
        int koff = ks * 256 + kc * 64;
        __syncthreads();
        for (int i = tid; i < 512; i += 256) {
            int r = i >> 4, c4 = i & 15;
            int bt = bt0 + r;
            float4 vv = make_float4(0.f, 0.f, 0.f, 0.f);
            if (bt < 1000) vv = *(const float4*)(g_buf2 + (size_t)bt * 1024 + koff + c4 * 4);
            *(float4*)&xs[r][c4 * 4] = vv;
        }
        for (int i = tid; i < 4096; i += 256) {   // transpose w3 chunk into smem
            int o = i >> 6, k = i & 63;
            ws[k][o] = w3[o * 1024 + koff + k];
        }
        __syncthreads();
#pragma unroll 16
        for (int k = 0; k < 64; k++) {
            float a0 = xs[2 * rp][k], a1 = xs[2 * rp + 1][k];
#pragma unroll
            for (int j = 0; j < 4; j++) {
                float wv = ws[k][oq + 16 * j];
                acc[0][j] = fmaf(a0, wv, acc[0][j]);
                acc[1][j] = fmaf(a1, wv, acc[1][j]);
            }
        }
    }
#pragma unroll
    for (int r = 0; r < 2; r++) {
        int bt = bt0 + 2 * rp + r;
        if (bt < 1000) {
#pragma unroll
            for (int j = 0; j < 4; j++)
                g_zpart[((size_t)bt * 4 + ks) * 64 + oq + 16 * j] = acc[r][j];
        }
    }
}

// ---------------------------------------------------------------------------
// Stage C2: contiguous gather + barrier-free scans (per-cell IAF is
// independent across t). grid = 25 (b), block = 256. 3 barriers total.
// ---------------------------------------------------------------------------
__global__ __launch_bounds__(256) void kC2(const float* __restrict__ w4,
                                           float* __restrict__ out) {
    const int b = blockIdx.x;
    const int tid = threadIdx.x;
    __shared__ float zs[NT * 64];    // z1[t][cell]
    __shared__ float ss[NT * 64];    // spikes1[t][cell]
    __shared__ float z2[NT * 11];    // fc2 pre-activations
    __shared__ float w4s[11 * 65];   // padded

    // contiguous load + k-split reduce: [40][4][64] -> [40][64]
    const float* p0 = g_zpart + (size_t)b * NT * 256;
    for (int i = tid; i < 640; i += 256) {
        int t = i >> 4, c4 = i & 15;
        const float* q = p0 + t * 256 + c4 * 4;
        float4 a = *(const float4*)(q);
        float4 c = *(const float4*)(q + 64);
        float4 d = *(const float4*)(q + 128);
        float4 e = *(const float4*)(q + 192);
        *(float4*)&zs[t * 64 + c4 * 4] =
            make_float4(a.x + c.x + d.x + e.x, a.y + c.y + d.y + e.y,
                        a.z + c.z + d.z + e.z, a.w + c.w + d.w + e.w);
    }
    for (int i = tid; i < 704; i += 256) {
        int o = i >> 6, j = i & 63;
        w4s[o * 65 + j] = w4[i];
    }
    __syncthreads();

    // Phase 1: per-cell IAF scan, barrier-free
    if (tid < 64) {
        float v1 = 0.f;
#pragma unroll 8
        for (int t = 0; t < NT; t++) {
            float vv = v1 + zs[t * 64 + tid];
            float s  = (vv >= 1.0f) ? 1.0f : 0.0f;
            vv = (s != 0.f) ? 0.f : vv;
            v1 = fmaxf(vv, -1.0f);
            ss[t * 64 + tid] = s;
        }
    }
    __syncthreads();

    // Phase 2: z2[t][o] = ss[t][:] . w4[o][:]
    for (int i = tid; i < NT * 11; i += 256) {
        int t = i / 11, o = i - 11 * t;
        const float* sp = &ss[t * 64];
        const float* wp = &w4s[o * 65];
        float za = 0.f, zb = 0.f, zc = 0.f, zd = 0.f;
#pragma unroll
        for (int j = 0; j < 64; j += 4) {
            za = fmaf(sp[j],     wp[j],     za);
            zb = fmaf(sp[j + 1], wp[j + 1], zb);
            zc = fmaf(sp[j + 2], wp[j + 2], zc);
            zd = fmaf(sp[j + 3], wp[j + 3], zd);
        }
        z2[i] = (za + zb) + (zc + zd);
    }
    __syncthreads();

    // Phase 3: per-output IAF scan, barrier-free
    if (tid < 11) {
        float v2 = 0.f;
#pragma unroll 8
        for (int t = 0; t < NT; t++) {
            float vv2 = v2 + z2[t * 11 + tid];
            float s2  = (vv2 >= 1.0f) ? 1.0f : 0.0f;
            vv2 = (s2 != 0.f) ? 0.f : vv2;
            v2 = fmaxf(vv2, -1.0f);
            out[(b * NT + t) * 11 + tid] = s2;
        }
    }
}

// ---------------------------------------------------------------------------
extern "C" void kernel_launch(void* const* d_in, const int* in_sizes, int n_in,
                              void* d_out, int out_size) {
    (void)in_sizes; (void)n_in; (void)out_size;
    const float* x  = (const float*)d_in[0];
    const float* w1 = (const float*)d_in[1];
    const float* w2 = (const float*)d_in[2];
    const float* w3 = (const float*)d_in[3];
    const float* w4 = (const float*)d_in[4];
    float* out = (float*)d_out;

    kA<<<dim3(16, 25), 256>>>(x, w1);
    kB<<<dim3(4, 2, 25), 128>>>(w2);
    kC1<<<dim3(32, 4), 256>>>(w3);
    kC2<<<25, 256>>>(w4, out);
}

// round 14
// speedup vs baseline: 1.8826x; 1.0291x over previous
#include <cuda_runtime.h>
#include <cstdint>

#define NB 25
#define NT 40

// Scratch (static device arrays — allocation-free per harness rules)
__device__ float g_buf1[1000 * 8 * 32 * 32];   // stage A pooled spikes [bt][8][32][32]
__device__ float g_buf2[1000 * 16 * 8 * 8];    // stage B pooled spikes [bt][1024]
__device__ float g_zpart[1000 * 4 * 64];       // fc1 partials [bt][ks][64]

__device__ __forceinline__ void cp16(uint32_t dst, const void* src, int bytes) {
    asm volatile("cp.async.cg.shared.global [%0], [%1], 16, %2;\n"
                 :: "r"(dst), "l"(src), "r"(bytes));
}
__device__ __forceinline__ void cp_commit() { asm volatile("cp.async.commit_group;\n" ::); }
__device__ __forceinline__ void cp_wait1()  { asm volatile("cp.async.wait_group 1;\n" ::); }
__device__ __forceinline__ void cp_wait2()  { asm volatile("cp.async.wait_group 2;\n" ::); }
__device__ __forceinline__ uint32_t saddr(const void* p) {
    return (uint32_t)__cvta_generic_to_shared(p);
}

// ---- packed f32x2 helpers (sm_103a) ---------------------------------------
__device__ __forceinline__ unsigned long long pk2(float lo, float hi) {
    unsigned long long r;
    asm("mov.b64 %0, {%1, %2};" : "=l"(r) : "f"(lo), "f"(hi));
    return r;
}
__device__ __forceinline__ unsigned long long bcast2(float x) {
    unsigned long long r;
    asm("mov.b64 %0, {%1, %1};" : "=l"(r) : "f"(x));
    return r;
}
__device__ __forceinline__ void fma2(unsigned long long& d,
                                     unsigned long long a, unsigned long long b) {
    asm("fma.rn.f32x2 %0, %1, %2, %0;" : "+l"(d) : "l"(a), "l"(b));
}
__device__ __forceinline__ void unpk2(unsigned long long v, float& lo, float& hi) {
    asm("mov.b64 {%0, %1}, %2;" : "=f"(lo), "=f"(hi) : "l"(v));
}

// ---------------------------------------------------------------------------
// Stage A: conv1 (2->8, 3x3, s2, p1) + IAF over T + 2x2 avgpool, fused.
// grid = (16 row-tiles, 25 b), block = 256, 2 CTAs/SM. (unchanged from R13)
// ---------------------------------------------------------------------------
__global__ __launch_bounds__(256, 2) void kA(const float* __restrict__ x,
                                             const float* __restrict__ w1) {
    const int tr = blockIdx.x;   // output rows [4*tr, 4*tr+4)
    const int b  = blockIdx.y;
    const int tid = threadIdx.x;

    __shared__ float sw[144];
    __shared__ __align__(16) float sx[4][2][9][132]; // [buf][ic][r][4+iw]; [3]=pad

    if (tid < 144) sw[tid] = w1[tid];
    if (tid < 72) { int bu = tid / 18, r = tid % 18; sx[bu][r / 9][r % 9][3] = 0.f; }

    // tid bits: [0:3]=pcl, [4]=rowlsb, [5]=pch, [6]=rowhi, [7]=og
    const int pcl    = tid & 15;
    const int rowlsb = (tid >> 4) & 1;
    const int pch    = (tid >> 5) & 1;
    const int rowhi  = (tid >> 6) & 1;
    const int og     = (tid >> 7) & 1;
    const int pc  = pcl + 16 * pch;      // pool col 0..31 (= pair ow 2pc,2pc+1)
    const int row = rowlsb + 2 * rowhi;  // local output row 0..3
    const int ihb = 8 * tr - 1;

    // load slots: 2ch x 9row x 32 float4 = 576 over 256 threads
    int sch[3], sr[3], sc[3], sih[3]; bool sact[3];
#pragma unroll
    for (int k = 0; k < 3; k++) {
        int i = tid + k * 256;
        sact[k] = (i < 576);
        int ii = sact[k] ? i : 0;
        sch[k] = (ii >= 288) ? 1 : 0;
        int rem = ii - sch[k] * 288;
        sr[k] = rem >> 5; sc[k] = rem & 31; sih[k] = ihb + sr[k];
    }

    auto issue = [&](int t, int bu) {
        const float* xp = x + (size_t)(b * NT + t) * 32768;
#pragma unroll
        for (int k = 0; k < 3; k++) {
            if (!sact[k]) continue;
            int ih = (sih[k] < 0) ? 0 : sih[k];
            int by = ((unsigned)sih[k] < 128u) ? 16 : 0;
            cp16(saddr(&sx[bu][sch[k]][sr[k]][4 + sc[k] * 4]),
                 xp + (sch[k] * 128 + ih) * 128 + sc[k] * 4, by);
        }
    };

    issue(0, 0); cp_commit();
    issue(1, 1); cp_commit();
    __syncthreads();   // sw + pads visible

    // packed weights: wq[ic][kh][kw][p] = {w(oc=og*4+2p), w(oc=og*4+2p+1)}
    unsigned long long wq[2][3][3][2];
#pragma unroll
    for (int ic = 0; ic < 2; ic++)
#pragma unroll
      for (int kh = 0; kh < 3; kh++)
#pragma unroll
        for (int kw = 0; kw < 3; kw++)
#pragma unroll
          for (int p = 0; p < 2; p++) {
            float wlo = sw[(((og * 4 + 2 * p)     * 2 + ic) * 3 + kh) * 3 + kw];
            float whi = sw[(((og * 4 + 2 * p + 1) * 2 + ic) * 3 + kh) * 3 + kw];
            wq[ic][kh][kw][p] = pk2(wlo, whi);
          }

    float v[2][4];
#pragma unroll
    for (int px = 0; px < 2; px++)
#pragma unroll
      for (int i = 0; i < 4; i++) v[px][i] = 0.f;

    float* const outbase = g_buf1 + (size_t)b * NT * 8192
                         + (og * 4) * 1024 + (2 * tr + rowhi) * 32 + pc;

    auto compute = [&](int bu, int t) {
        unsigned long long a2[2][2];      // [px][pair]
        a2[0][0] = a2[0][1] = a2[1][0] = a2[1][1] = 0ull;
#pragma unroll
        for (int ic = 0; ic < 2; ic++)
#pragma unroll
          for (int kh = 0; kh < 3; kh++) {
            const float* rp = &sx[bu][ic][2 * row + kh][0];
            float  xm = rp[3 + 4 * pc];
            float4 r4 = *(const float4*)&rp[4 + 4 * pc];
            unsigned long long X;
            X = bcast2(xm);
            fma2(a2[0][0], X, wq[ic][kh][0][0]);
            fma2(a2[0][1], X, wq[ic][kh][0][1]);
            X = bcast2(r4.x);
            fma2(a2[0][0], X, wq[ic][kh][1][0]);
            fma2(a2[0][1], X, wq[ic][kh][1][1]);
            X = bcast2(r4.y);
            fma2(a2[0][0], X, wq[ic][kh][2][0]);
            fma2(a2[0][1], X, wq[ic][kh][2][1]);
            fma2(a2[1][0], X, wq[ic][kh][0][0]);
            fma2(a2[1][1], X, wq[ic][kh][0][1]);
            X = bcast2(r4.z);
            fma2(a2[1][0], X, wq[ic][kh][1][0]);
            fma2(a2[1][1], X, wq[ic][kh][1][1]);
            X = bcast2(r4.w);
            fma2(a2[1][0], X, wq[ic][kh][2][0]);
            fma2(a2[1][1], X, wq[ic][kh][2][1]);
          }
        float acc[2][4];
#pragma unroll
        for (int px = 0; px < 2; px++) {
            unpk2(a2[px][0], acc[px][0], acc[px][1]);
            unpk2(a2[px][1], acc[px][2], acc[px][3]);
        }
        float* outp = outbase + (size_t)t * 8192;
#pragma unroll
        for (int i = 0; i < 4; i++) {
            float h = 0.f;
#pragma unroll
            for (int px = 0; px < 2; px++) {
                float vv = v[px][i] + acc[px][i];
                float s  = (vv >= 1.0f) ? 1.0f : 0.0f;
                vv = (s != 0.f) ? 0.f : vv;
                v[px][i] = fmaxf(vv, -1.0f);
                h += s;
            }
            h += __shfl_xor_sync(0xffffffffu, h, 16);   // vertical pair
            if (rowlsb == 0) outp[i * 1024] = h * 0.25f;
        }
    };

    for (int t = 0; t < NT; t += 2) {
        if (t + 2 < NT) issue(t + 2, (t + 2) & 3);
        cp_commit();
        if (t + 3 < NT) issue(t + 3, (t + 3) & 3);
        cp_commit();
        cp_wait2();
        __syncthreads();

        compute(t & 3, t);
        compute((t + 1) & 3, t + 1);
    }
}

// ---------------------------------------------------------------------------
// Stage B: conv2 (8->16, 3x3, s2, p1) + IAF + 2x2 avgpool, fused.
// grid = (8 row-tiles, 2 oc-splits, 25 b) = 400 CTAs, block = 64.
// 2 conv-out rows per CTA (one pool row); thread = 2px x 2oc (same math as
// R13 thread). All CTAs resident; per-SM max 3 small CTAs (was 2 big ones).
// ---------------------------------------------------------------------------
__global__ __launch_bounds__(64, 6) void kB(const float* __restrict__ w2) {
    const int tr = blockIdx.x;   // out rows 2*tr, 2*tr+1 (pool row tr)
    const int os = blockIdx.y;   // oc base = 8*os
    const int b  = blockIdx.z;
    const int tid = threadIdx.x;

    __shared__ float sw[576];
    __shared__ __align__(16) float sx[4][8][5][36]; // [buf][ic][r][4+iw]; [3]=pad

    for (int i = tid; i < 576; i += 64) sw[i] = w2[os * 576 + i];
    for (int i = tid; i < 160; i += 64) {           // pads: 4 bufs x 40 rows
        int bu = i / 40, r = i % 40;
        sx[bu][r / 5][r % 5][3] = 0.f;
    }

    // tid bits: [0:2]=pc, [3]=rowlsb, [4:5]=ocp
    const int pc     = tid & 7;
    const int rowlsb = (tid >> 3) & 1;
    const int ocp    = (tid >> 4) & 3;
    const int ihb = 4 * tr - 1;

    // load slots: 8 ic x 5 rows x 8 float4 = 320 = 5 x 64 (exact)
    int lch[5], lr[5], lc[5], lih[5];
#pragma unroll
    for (int k = 0; k < 5; k++) {
        int i = tid + k * 64;
        lch[k] = i / 40; int rem = i - lch[k] * 40;
        lr[k] = rem >> 3; lc[k] = rem & 7; lih[k] = ihb + lr[k];
    }

    auto issue = [&](int t, int bu) {
        const float* inp = g_buf1 + (size_t)(b * NT + t) * 8192;
#pragma unroll
        for (int k = 0; k < 5; k++) {
            int ih = (lih[k] < 0) ? 0 : lih[k];
            int by = ((unsigned)lih[k] < 32u) ? 16 : 0;
            cp16(saddr(&sx[bu][lch[k]][lr[k]][4 + lc[k] * 4]),
                 inp + (lch[k] * 32 + ih) * 32 + lc[k] * 4, by);
        }
    };

    issue(0, 0); cp_commit();
    issue(1, 1); cp_commit();
    __syncthreads();

    // weights: 2 ocs per thread (oc = os*8 + ocp*2 + j); w2 row = 72 floats
    float wrg[8][3][3][2];
#pragma unroll
    for (int ic = 0; ic < 8; ic++)
#pragma unroll
      for (int kh = 0; kh < 3; kh++)
#pragma unroll
        for (int kw = 0; kw < 3; kw++)
#pragma unroll
          for (int j = 0; j < 2; j++)
            wrg[ic][kh][kw][j] = sw[(ocp * 2 + j) * 72 + ic * 9 + kh * 3 + kw];

    float v[2][2];
    v[0][0] = v[0][1] = v[1][0] = v[1][1] = 0.f;

    // direct-store base: g_buf2[bt][os*8+ocp*2+j][tr*8 + pc]
    float* const outbase = g_buf2 + (size_t)b * NT * 1024
                         + (os * 8 + ocp * 2) * 64 + tr * 8 + pc;

    auto compute = [&](int bu, int t) {
        float acc[2][2];
        acc[0][0] = acc[0][1] = acc[1][0] = acc[1][1] = 0.f;
#pragma unroll
        for (int ic = 0; ic < 8; ic++)
#pragma unroll
          for (int kh = 0; kh < 3; kh++) {
            const float* rp = &sx[bu][ic][2 * rowlsb + kh][0];
            float  xm = rp[3 + 4 * pc];
            float4 r4 = *(const float4*)&rp[4 + 4 * pc];
#pragma unroll
            for (int j = 0; j < 2; j++) {
                float w0 = wrg[ic][kh][0][j], w1r = wrg[ic][kh][1][j], w2r = wrg[ic][kh][2][j];
                acc[0][j] = fmaf(xm,   w0,  acc[0][j]);
                acc[0][j] = fmaf(r4.x, w1r, acc[0][j]);
                acc[0][j] = fmaf(r4.y, w2r, acc[0][j]);
                acc[1][j] = fmaf(r4.y, w0,  acc[1][j]);
                acc[1][j] = fmaf(r4.z, w1r, acc[1][j]);
                acc[1][j] = fmaf(r4.w, w2r, acc[1][j]);
            }
          }
        float* outp = outbase + (size_t)t * 1024;
#pragma unroll
        for (int j = 0; j < 2; j++) {
            float h = 0.f;
#pragma unroll
            for (int px = 0; px < 2; px++) {
                float vv = v[px][j] + acc[px][j];
                float s  = (vv >= 1.0f) ? 1.0f : 0.0f;
                vv = (s != 0.f) ? 0.f : vv;
                v[px][j] = fmaxf(vv, -1.0f);
                h += s;
            }
            h += __shfl_xor_sync(0xffffffffu, h, 8);   // vertical pair (rowlsb)
            if (rowlsb == 0) outp[j * 64] = h * 0.25f;
        }
    };

    for (int t = 0; t < NT; t += 2) {
        if (t + 2 < NT) issue(t + 2, (t + 2) & 3);
        cp_commit();
        if (t + 3 < NT) issue(t + 3, (t + 3) & 3);
        cp_commit();
        cp_wait2();
        __syncthreads();

        compute(t & 3, t);
        compute((t + 1) & 3, t + 1);
    }
}

// ---------------------------------------------------------------------------
// Stage C1: fc1 partial GEMM  z[bt,64] = buf2[bt,1024] @ w3^T, k-split x4.
// grid = (32 bt-tiles of 32 rows, 4 k-splits), block 256, thread tile 2x4.
// Double-buffered: xs via cp.async (zero-fill OOB), w3 via register prefetch;
// one barrier per k-chunk. Dyn smem: xs[2][32][64]@0, ws[2][64][65]@4096.
// ---------------------------------------------------------------------------
#define KC1_SMEM_FLOATS (4096 + 2 * 64 * 65)
__global__ __launch_bounds__(256) void kC1(const float* __restrict__ w3) {
    extern __shared__ float smC[];
    float* xs = smC;            // [2][32][64]
    float* ws = smC + 4096;     // [2][64][65]

    const int bt0 = blockIdx.x * 32;
    const int ks  = blockIdx.y;
    const int tid = threadIdx.x;
    const int rp = tid >> 4, oq = tid & 15;

    auto issue_xs = [&](int kc, int bu) {
        int koff = ks * 256 + kc * 64;
#pragma unroll
        for (int k = 0; k < 2; k++) {
            int i = tid + k * 256;
            int r = i >> 4, c4 = i & 15;
            int bt = bt0 + r;
            int by = (bt < 1000) ? 16 : 0;
            int btc = (bt < 1000) ? bt : 0;
            cp16(saddr(&xs[(bu * 32 + r) * 64 + c4 * 4]),
                 g_buf2 + (size_t)btc * 1024 + koff + c4 * 4, by);
        }
    };

    float wr[16];
    auto ldw = [&](int kc) {
        int koff = ks * 256 + kc * 64;
#pragma unroll
        for (int k = 0; k < 16; k++) {
            int i = tid + k * 256;
            int o = i >> 6, kk = i & 63;
            wr[k] = w3[o * 1024 + koff + kk];
        }
    };
    auto stw = [&](int bu) {
#pragma unroll
        for (int k = 0; k < 16; k++) {
            int i = tid + k * 256;
            int o = i >> 6, kk = i & 63;
            ws[bu * 4160 + kk * 65 + o] = wr[k];
        }
    };

    issue_xs(0, 0); cp_commit();
    ldw(0);

    float acc[2][4];
#pragma unroll
    for (int r = 0; r < 2; r++)
#pragma unroll
      for (int j = 0; j < 4; j++) acc[r][j] = 0.f;

    for (int kc = 0; kc < 4; kc++) {
        const int cur = kc & 1;
        stw(cur);
        if (kc + 1 < 4) issue_xs(kc + 1, cur ^ 1);
        cp_commit();                 // uniform group count
        if (kc + 1 < 4) ldw(kc + 1); // LDGs fly during compute
        cp_wait1();                  // chunk kc complete (this thread)
        __syncthreads();             // xs[cur] + ws[cur] visible to all

#pragma unroll 16
        for (int k = 0; k < 64; k++) {
            float a0 = xs[(cur * 32 + 2 * rp) * 64 + k];
            float a1 = xs[(cur * 32 + 2 * rp + 1) * 64 + k];
#pragma unroll
            for (int j = 0; j < 4; j++) {
                float wv = ws[cur * 4160 + k * 65 + oq + 16 * j];
                acc[0][j] = fmaf(a0, wv, acc[0][j]);
                acc[1][j] = fmaf(a1, wv, acc[1][j]);
            }
        }
        // no trailing barrier: next iter writes only the OTHER buffers
    }
#pragma unroll
    for (int r = 0; r < 2; r++) {
        int bt = bt0 + 2 * rp + r;
        if (bt < 1000) {
#pragma unroll
            for (int j = 0; j < 4; j++)
                g_zpart[((size_t)bt * 4 + ks) * 64 + oq + 16 * j] = acc[r][j];
        }
    }
}

// ---------------------------------------------------------------------------
// Stage C2: contiguous gather + barrier-free scans. grid = 25, block = 256.
// (unchanged from R13)
// ---------------------------------------------------------------------------
__global__ __launch_bounds__(256) void kC2(const float* __restrict__ w4,
                                           float* __restrict__ out) {
    const int b = blockIdx.x;
    const int tid = threadIdx.x;
    __shared__ float zs[NT * 64];    // z1[t][cell]
    __shared__ float ss[NT * 64];    // spikes1[t][cell]
    __shared__ float z2[NT * 11];    // fc2 pre-activations
    __shared__ float w4s[11 * 65];   // padded

    const float* p0 = g_zpart + (size_t)b * NT * 256;
    for (int i = tid; i < 640; i += 256) {
        int t = i >> 4, c4 = i & 15;
        const float* q = p0 + t * 256 + c4 * 4;
        float4 a = *(const float4*)(q);
        float4 c = *(const float4*)(q + 64);
        float4 d = *(const float4*)(q + 128);
        float4 e = *(const float4*)(q + 192);
        *(float4*)&zs[t * 64 + c4 * 4] =
            make_float4(a.x + c.x + d.x + e.x, a.y + c.y + d.y + e.y,
                        a.z + c.z + d.z + e.z, a.w + c.w + d.w + e.w);
    }
    for (int i = tid; i < 704; i += 256) {
        int o = i >> 6, j = i & 63;
        w4s[o * 65 + j] = w4[i];
    }
    __syncthreads();

    if (tid < 64) {
        float v1 = 0.f;
#pragma unroll 8
        for (int t = 0; t < NT; t++) {
            float vv = v1 + zs[t * 64 + tid];
            float s  = (vv >= 1.0f) ? 1.0f : 0.0f;
            vv = (s != 0.f) ? 0.f : vv;
            v1 = fmaxf(vv, -1.0f);
            ss[t * 64 + tid] = s;
        }
    }
    __syncthreads();

    for (int i = tid; i < NT * 11; i += 256) {
        int t = i / 11, o = i - 11 * t;
        const float* sp = &ss[t * 64];
        const float* wp = &w4s[o * 65];
        float za = 0.f, zb = 0.f, zc = 0.f, zd = 0.f;
#pragma unroll
        for (int j = 0; j < 64; j += 4) {
            za = fmaf(sp[j],     wp[j],     za);
            zb = fmaf(sp[j + 1], wp[j + 1], zb);
            zc = fmaf(sp[j + 2], wp[j + 2], zc);
            zd = fmaf(sp[j + 3], wp[j + 3], zd);
        }
        z2[i] = (za + zb) + (zc + zd);
    }
    __syncthreads();

    if (tid < 11) {
        float v2 = 0.f;
#pragma unroll 8
        for (int t = 0; t < NT; t++) {
            float vv2 = v2 + z2[t * 11 + tid];
            float s2  = (vv2 >= 1.0f) ? 1.0f : 0.0f;
            vv2 = (s2 != 0.f) ? 0.f : vv2;
            v2 = fmaxf(vv2, -1.0f);
            out[(b * NT + t) * 11 + tid] = s2;
        }
    }
}

// ---------------------------------------------------------------------------
extern "C" void kernel_launch(void* const* d_in, const int* in_sizes, int n_in,
                              void* d_out, int out_size) {
    (void)in_sizes; (void)n_in; (void)out_size;
    const float* x  = (const float*)d_in[0];
    const float* w1 = (const float*)d_in[1];
    const float* w2 = (const float*)d_in[2];
    const float* w3 = (const float*)d_in[3];
    const float* w4 = (const float*)d_in[4];
    float* out = (float*)d_out;

    const int kc1Bytes = KC1_SMEM_FLOATS * 4;   // ~49.7 KB (dynamic)
    cudaFuncSetAttribute(kC1, cudaFuncAttributeMaxDynamicSharedMemorySize, kc1Bytes);

    kA<<<dim3(16, 25), 256>>>(x, w1);
    kB<<<dim3(8, 2, 25), 64>>>(w2);
    kC1<<<dim3(32, 4), 256, kc1Bytes>>>(w3);
    kC2<<<25, 256>>>(w4, out);
}

// round 16
// speedup vs baseline: 1.8977x; 1.0080x over previous
#include <cuda_runtime.h>
#include <cstdint>

#define NB 25
#define NT 40

// Scratch (static device arrays — allocation-free per harness rules)
__device__ float g_buf1[1000 * 8 * 32 * 32];   // stage A pooled spikes [bt][8][32][32]
__device__ float g_buf2[1000 * 16 * 8 * 8];    // stage B pooled spikes [bt][1024]
__device__ float g_zpart[1000 * 4 * 64];       // fc1 partials [bt][ks][64]

__device__ __forceinline__ void cp16(uint32_t dst, const void* src, int bytes) {
    asm volatile("cp.async.cg.shared.global [%0], [%1], 16, %2;\n"
                 :: "r"(dst), "l"(src), "r"(bytes));
}
__device__ __forceinline__ void cp_commit() { asm volatile("cp.async.commit_group;\n" ::); }
__device__ __forceinline__ void cp_wait1()  { asm volatile("cp.async.wait_group 1;\n" ::); }
__device__ __forceinline__ void cp_wait2()  { asm volatile("cp.async.wait_group 2;\n" ::); }
__device__ __forceinline__ uint32_t saddr(const void* p) {
    return (uint32_t)__cvta_generic_to_shared(p);
}

// ---- packed f32x2 helpers (sm_103a) ---------------------------------------
__device__ __forceinline__ unsigned long long pk2(float lo, float hi) {
    unsigned long long r;
    asm("mov.b64 %0, {%1, %2};" : "=l"(r) : "f"(lo), "f"(hi));
    return r;
}
__device__ __forceinline__ unsigned long long bcast2(float x) {
    unsigned long long r;
    asm("mov.b64 %0, {%1, %1};" : "=l"(r) : "f"(x));
    return r;
}
__device__ __forceinline__ void fma2(unsigned long long& d,
                                     unsigned long long a, unsigned long long b) {
    asm("fma.rn.f32x2 %0, %1, %2, %0;" : "+l"(d) : "l"(a), "l"(b));
}
__device__ __forceinline__ void unpk2(unsigned long long v, float& lo, float& hi) {
    asm("mov.b64 {%0, %1}, %2;" : "=f"(lo), "=f"(hi) : "l"(v));
}

// ---------------------------------------------------------------------------
// Stage A: conv1 (2->8, 3x3, s2, p1) + IAF over T + 2x2 avgpool, fused.
// grid = (16 row-tiles, 25 b), block = 256, 2 CTAs/SM. (R14 math, unchanged)
// ---------------------------------------------------------------------------
__global__ __launch_bounds__(256, 2) void kA(const float* __restrict__ x,
                                             const float* __restrict__ w1) {
    const int tr = blockIdx.x;   // output rows [4*tr, 4*tr+4)
    const int b  = blockIdx.y;
    const int tid = threadIdx.x;

    __shared__ float sw[144];
    __shared__ __align__(16) float sx[4][2][9][132]; // [buf][ic][r][4+iw]; [3]=pad

    if (tid < 144) sw[tid] = w1[tid];
    if (tid < 72) { int bu = tid / 18, r = tid % 18; sx[bu][r / 9][r % 9][3] = 0.f; }

    // tid bits: [0:3]=pcl, [4]=rowlsb, [5]=pch, [6]=rowhi, [7]=og
    const int pcl    = tid & 15;
    const int rowlsb = (tid >> 4) & 1;
    const int pch    = (tid >> 5) & 1;
    const int rowhi  = (tid >> 6) & 1;
    const int og     = (tid >> 7) & 1;
    const int pc  = pcl + 16 * pch;      // pool col 0..31 (= pair ow 2pc,2pc+1)
    const int row = rowlsb + 2 * rowhi;  // local output row 0..3
    const int ihb = 8 * tr - 1;

    // load slots: 2ch x 9row x 32 float4 = 576 over 256 threads
    int sch[3], sr[3], sc[3], sih[3]; bool sact[3];
#pragma unroll
    for (int k = 0; k < 3; k++) {
        int i = tid + k * 256;
        sact[k] = (i < 576);
        int ii = sact[k] ? i : 0;
        sch[k] = (ii >= 288) ? 1 : 0;
        int rem = ii - sch[k] * 288;
        sr[k] = rem >> 5; sc[k] = rem & 31; sih[k] = ihb + sr[k];
    }

    auto issue = [&](int t, int bu) {
        const float* xp = x + (size_t)(b * NT + t) * 32768;
#pragma unroll
        for (int k = 0; k < 3; k++) {
            if (!sact[k]) continue;
            int ih = (sih[k] < 0) ? 0 : sih[k];
            int by = ((unsigned)sih[k] < 128u) ? 16 : 0;
            cp16(saddr(&sx[bu][sch[k]][sr[k]][4 + sc[k] * 4]),
                 xp + (sch[k] * 128 + ih) * 128 + sc[k] * 4, by);
        }
    };

    issue(0, 0); cp_commit();
    issue(1, 1); cp_commit();
    __syncthreads();   // sw + pads visible

    // packed weights: wq[ic][kh][kw][p] = {w(oc=og*4+2p), w(oc=og*4+2p+1)}
    unsigned long long wq[2][3][3][2];
#pragma unroll
    for (int ic = 0; ic < 2; ic++)
#pragma unroll
      for (int kh = 0; kh < 3; kh++)
#pragma unroll
        for (int kw = 0; kw < 3; kw++)
#pragma unroll
          for (int p = 0; p < 2; p++) {
            float wlo = sw[(((og * 4 + 2 * p)     * 2 + ic) * 3 + kh) * 3 + kw];
            float whi = sw[(((og * 4 + 2 * p + 1) * 2 + ic) * 3 + kh) * 3 + kw];
            wq[ic][kh][kw][p] = pk2(wlo, whi);
          }

    float v[2][4];
#pragma unroll
    for (int px = 0; px < 2; px++)
#pragma unroll
      for (int i = 0; i < 4; i++) v[px][i] = 0.f;

    float* const outbase = g_buf1 + (size_t)b * NT * 8192
                         + (og * 4) * 1024 + (2 * tr + rowhi) * 32 + pc;

    auto compute = [&](int bu, int t) {
        unsigned long long a2[2][2];      // [px][pair]
        a2[0][0] = a2[0][1] = a2[1][0] = a2[1][1] = 0ull;
#pragma unroll
        for (int ic = 0; ic < 2; ic++)
#pragma unroll
          for (int kh = 0; kh < 3; kh++) {
            const float* rp = &sx[bu][ic][2 * row + kh][0];
            float  xm = rp[3 + 4 * pc];
            float4 r4 = *(const float4*)&rp[4 + 4 * pc];
            unsigned long long X;
            X = bcast2(xm);
            fma2(a2[0][0], X, wq[ic][kh][0][0]);
            fma2(a2[0][1], X, wq[ic][kh][0][1]);
            X = bcast2(r4.x);
            fma2(a2[0][0], X, wq[ic][kh][1][0]);
            fma2(a2[0][1], X, wq[ic][kh][1][1]);
            X = bcast2(r4.y);
            fma2(a2[0][0], X, wq[ic][kh][2][0]);
            fma2(a2[0][1], X, wq[ic][kh][2][1]);
            fma2(a2[1][0], X, wq[ic][kh][0][0]);
            fma2(a2[1][1], X, wq[ic][kh][0][1]);
            X = bcast2(r4.z);
            fma2(a2[1][0], X, wq[ic][kh][1][0]);
            fma2(a2[1][1], X, wq[ic][kh][1][1]);
            X = bcast2(r4.w);
            fma2(a2[1][0], X, wq[ic][kh][2][0]);
            fma2(a2[1][1], X, wq[ic][kh][2][1]);
          }
        float acc[2][4];
#pragma unroll
        for (int px = 0; px < 2; px++) {
            unpk2(a2[px][0], acc[px][0], acc[px][1]);
            unpk2(a2[px][1], acc[px][2], acc[px][3]);
        }
        float* outp = outbase + (size_t)t * 8192;
#pragma unroll
        for (int i = 0; i < 4; i++) {
            float h = 0.f;
#pragma unroll
            for (int px = 0; px < 2; px++) {
                float vv = v[px][i] + acc[px][i];
                float s  = (vv >= 1.0f) ? 1.0f : 0.0f;
                vv = (s != 0.f) ? 0.f : vv;
                v[px][i] = fmaxf(vv, -1.0f);
                h += s;
            }
            h += __shfl_xor_sync(0xffffffffu, h, 16);   // vertical pair
            if (rowlsb == 0) outp[i * 1024] = h * 0.25f;
        }
    };

    for (int t = 0; t < NT; t += 2) {
        if (t + 2 < NT) issue(t + 2, (t + 2) & 3);
        cp_commit();
        if (t + 3 < NT) issue(t + 3, (t + 3) & 3);
        cp_commit();
        cp_wait2();
        __syncthreads();

        compute(t & 3, t);
        compute((t + 1) & 3, t + 1);
    }

    // PDL: signal that this block is done (fires when ALL blocks reach here)
    cudaTriggerProgrammaticLaunchCompletion();
}

// ---------------------------------------------------------------------------
// Stage B: conv2 (8->16, 3x3, s2, p1) + IAF + 2x2 avgpool, fused.
// grid = (8 row-tiles, 2 oc-splits, 25 b) = 400 CTAs, block = 64.
// (R14 math unchanged; PDL: independent preamble before griddepsync.)
// ---------------------------------------------------------------------------
__global__ __launch_bounds__(64, 6) void kB(const float* __restrict__ w2) {
    const int tr = blockIdx.x;   // out rows 2*tr, 2*tr+1 (pool row tr)
    const int os = blockIdx.y;   // oc base = 8*os
    const int b  = blockIdx.z;
    const int tid = threadIdx.x;

    __shared__ float sw[576];
    __shared__ __align__(16) float sx[4][8][5][36]; // [buf][ic][r][4+iw]; [3]=pad

    // ---- independent preamble (w2 + smem pads + index setup) ----
    for (int i = tid; i < 576; i += 64) sw[i] = w2[os * 576 + i];
    for (int i = tid; i < 160; i += 64) {           // pads: 4 bufs x 40 rows
        int bu = i / 40, r = i % 40;
        sx[bu][r / 5][r % 5][3] = 0.f;
    }

    // tid bits: [0:2]=pc, [3]=rowlsb, [4:5]=ocp
    const int pc     = tid & 7;
    const int rowlsb = (tid >> 3) & 1;
    const int ocp    = (tid >> 4) & 3;
    const int ihb = 4 * tr - 1;

    // load slots: 8 ic x 5 rows x 8 float4 = 320 = 5 x 64 (exact)
    int lch[5], lr[5], lc[5], lih[5];
#pragma unroll
    for (int k = 0; k < 5; k++) {
        int i = tid + k * 64;
        lch[k] = i / 40; int rem = i - lch[k] * 40;
        lr[k] = rem >> 3; lc[k] = rem & 7; lih[k] = ihb + lr[k];
    }

    // ---- wait for kA's grid (g_buf1 producer) to complete ----
    cudaGridDependencySynchronize();

    auto issue = [&](int t, int bu) {
        const float* inp = g_buf1 + (size_t)(b * NT + t) * 8192;
#pragma unroll
        for (int k = 0; k < 5; k++) {
            int ih = (lih[k] < 0) ? 0 : lih[k];
            int by = ((unsigned)lih[k] < 32u) ? 16 : 0;
            cp16(saddr(&sx[bu][lch[k]][lr[k]][4 + lc[k] * 4]),
                 inp + (lch[k] * 32 + ih) * 32 + lc[k] * 4, by);
        }
    };

    issue(0, 0); cp_commit();
    issue(1, 1); cp_commit();
    __syncthreads();

    // weights: 2 ocs per thread (oc = os*8 + ocp*2 + j); w2 row = 72 floats
    float wrg[8][3][3][2];
#pragma unroll
    for (int ic = 0; ic < 8; ic++)
#pragma unroll
      for (int kh = 0; kh < 3; kh++)
#pragma unroll
        for (int kw = 0; kw < 3; kw++)
#pragma unroll
          for (int j = 0; j < 2; j++)
            wrg[ic][kh][kw][j] = sw[(ocp * 2 + j) * 72 + ic * 9 + kh * 3 + kw];

    float v[2][2];
    v[0][0] = v[0][1] = v[1][0] = v[1][1] = 0.f;

    // direct-store base: g_buf2[bt][os*8+ocp*2+j][tr*8 + pc]
    float* const outbase = g_buf2 + (size_t)b * NT * 1024
                         + (os * 8 + ocp * 2) * 64 + tr * 8 + pc;

    auto compute = [&](int bu, int t) {
        float acc[2][2];
        acc[0][0] = acc[0][1] = acc[1][0] = acc[1][1] = 0.f;
#pragma unroll
        for (int ic = 0; ic < 8; ic++)
#pragma unroll
          for (int kh = 0; kh < 3; kh++) {
            const float* rp = &sx[bu][ic][2 * rowlsb + kh][0];
            float  xm = rp[3 + 4 * pc];
            float4 r4 = *(const float4*)&rp[4 + 4 * pc];
#pragma unroll
            for (int j = 0; j < 2; j++) {
                float w0 = wrg[ic][kh][0][j], w1r = wrg[ic][kh][1][j], w2r = wrg[ic][kh][2][j];
                acc[0][j] = fmaf(xm,   w0,  acc[0][j]);
                acc[0][j] = fmaf(r4.x, w1r, acc[0][j]);
                acc[0][j] = fmaf(r4.y, w2r, acc[0][j]);
                acc[1][j] = fmaf(r4.y, w0,  acc[1][j]);
                acc[1][j] = fmaf(r4.z, w1r, acc[1][j]);
                acc[1][j] = fmaf(r4.w, w2r, acc[1][j]);
            }
          }
        float* outp = outbase + (size_t)t * 1024;
#pragma unroll
        for (int j = 0; j < 2; j++) {
            float h = 0.f;
#pragma unroll
            for (int px = 0; px < 2; px++) {
                float vv = v[px][j] + acc[px][j];
                float s  = (vv >= 1.0f) ? 1.0f : 0.0f;
                vv = (s != 0.f) ? 0.f : vv;
                v[px][j] = fmaxf(vv, -1.0f);
                h += s;
            }
            h += __shfl_xor_sync(0xffffffffu, h, 8);   // vertical pair (rowlsb)
            if (rowlsb == 0) outp[j * 64] = h * 0.25f;
        }
    };

    for (int t = 0; t < NT; t += 2) {
        if (t + 2 < NT) issue(t + 2, (t + 2) & 3);
        cp_commit();
        if (t + 3 < NT) issue(t + 3, (t + 3) & 3);
        cp_commit();
        cp_wait2();
        __syncthreads();

        compute(t & 3, t);
        compute((t + 1) & 3, t + 1);
    }

    cudaTriggerProgrammaticLaunchCompletion();
}

// ---------------------------------------------------------------------------
// Stage C1: fc1 partial GEMM  z[bt,64] = buf2[bt,1024] @ w3^T, k-split x4.
// grid = (32 bt-tiles of 32 rows, 4 k-splits), block 256, thread tile 2x4.
// Double-buffered; PDL: w3 register prefetch before griddepsync.
// ---------------------------------------------------------------------------
#define KC1_SMEM_FLOATS (4096 + 2 * 64 * 65)
__global__ __launch_bounds__(256) void kC1(const float* __restrict__ w3) {
    extern __shared__ float smC[];
    float* xs = smC;            // [2][32][64]
    float* ws = smC + 4096;     // [2][64][65]

    const int bt0 = blockIdx.x * 32;
    const int ks  = blockIdx.y;
    const int tid = threadIdx.x;
    const int rp = tid >> 4, oq = tid & 15;

    auto issue_xs = [&](int kc, int bu) {
        int koff = ks * 256 + kc * 64;
#pragma unroll
        for (int k = 0; k < 2; k++) {
            int i = tid + k * 256;
            int r = i >> 4, c4 = i & 15;
            int bt = bt0 + r;
            int by = (bt < 1000) ? 16 : 0;
            int btc = (bt < 1000) ? bt : 0;
            cp16(saddr(&xs[(bu * 32 + r) * 64 + c4 * 4]),
                 g_buf2 + (size_t)btc * 1024 + koff + c4 * 4, by);
        }
    };

    float wr[16];
    auto ldw = [&](int kc) {
        int koff = ks * 256 + kc * 64;
#pragma unroll
        for (int k = 0; k < 16; k++) {
            int i = tid + k * 256;
            int o = i >> 6, kk = i & 63;
            wr[k] = w3[o * 1024 + koff + kk];
        }
    };
    auto stw = [&](int bu) {
#pragma unroll
        for (int k = 0; k < 16; k++) {
            int i = tid + k * 256;
            int o = i >> 6, kk = i & 63;
            ws[bu * 4160 + kk * 65 + o] = wr[k];
        }
    };

    // independent preamble: first w3 chunk in flight before the dependency
    ldw(0);
    cudaGridDependencySynchronize();
    issue_xs(0, 0); cp_commit();

    float acc[2][4];
#pragma unroll
    for (int r = 0; r < 2; r++)
#pragma unroll
      for (int j = 0; j < 4; j++) acc[r][j] = 0.f;

    for (int kc = 0; kc < 4; kc++) {
        const int cur = kc & 1;
        stw(cur);
        if (kc + 1 < 4) issue_xs(kc + 1, cur ^ 1);
        cp_commit();
        if (kc + 1 < 4) ldw(kc + 1);
        cp_wait1();
        __syncthreads();

#pragma unroll 16
        for (int k = 0; k < 64; k++) {
            float a0 = xs[(cur * 32 + 2 * rp) * 64 + k];
            float a1 = xs[(cur * 32 + 2 * rp + 1) * 64 + k];
#pragma unroll
            for (int j = 0; j < 4; j++) {
                float wv = ws[cur * 4160 + k * 65 + oq + 16 * j];
                acc[0][j] = fmaf(a0, wv, acc[0][j]);
                acc[1][j] = fmaf(a1, wv, acc[1][j]);
            }
        }
    }
#pragma unroll
    for (int r = 0; r < 2; r++) {
        int bt = bt0 + 2 * rp + r;
        if (bt < 1000) {
#pragma unroll
            for (int j = 0; j < 4; j++)
                g_zpart[((size_t)bt * 4 + ks) * 64 + oq + 16 * j] = acc[r][j];
        }
    }

    cudaTriggerProgrammaticLaunchCompletion();
}

// ---------------------------------------------------------------------------
// Stage C2: contiguous gather + barrier-free scans. grid = 25, block = 256.
// PDL: w4 load before griddepsync.
// ---------------------------------------------------------------------------
__global__ __launch_bounds__(256) void kC2(const float* __restrict__ w4,
                                           float* __restrict__ out) {
    const int b = blockIdx.x;
    const int tid = threadIdx.x;
    __shared__ float zs[NT * 64];
    __shared__ float ss[NT * 64];
    __shared__ float z2[NT * 11];
    __shared__ float w4s[11 * 65];

    // independent preamble: fc2 weights
    for (int i = tid; i < 704; i += 256) {
        int o = i >> 6, j = i & 63;
        w4s[o * 65 + j] = w4[i];
    }

    cudaGridDependencySynchronize();

    const float* p0 = g_zpart + (size_t)b * NT * 256;
    for (int i = tid; i < 640; i += 256) {
        int t = i >> 4, c4 = i & 15;
        const float* q = p0 + t * 256 + c4 * 4;
        float4 a = *(const float4*)(q);
        float4 c = *(const float4*)(q + 64);
        float4 d = *(const float4*)(q + 128);
        float4 e = *(const float4*)(q + 192);
        *(float4*)&zs[t * 64 + c4 * 4] =
            make_float4(a.x + c.x + d.x + e.x, a.y + c.y + d.y + e.y,
                        a.z + c.z + d.z + e.z, a.w + c.w + d.w + e.w);
    }
    __syncthreads();

    if (tid < 64) {
        float v1 = 0.f;
#pragma unroll 8
        for (int t = 0; t < NT; t++) {
            float vv = v1 + zs[t * 64 + tid];
            float s  = (vv >= 1.0f) ? 1.0f : 0.0f;
            vv = (s != 0.f) ? 0.f : vv;
            v1 = fmaxf(vv, -1.0f);
            ss[t * 64 + tid] = s;
        }
    }
    __syncthreads();

    for (int i = tid; i < NT * 11; i += 256) {
        int t = i / 11, o = i - 11 * t;
        const float* sp = &ss[t * 64];
        const float* wp = &w4s[o * 65];
        float za = 0.f, zb = 0.f, zc = 0.f, zd = 0.f;
#pragma unroll
        for (int j = 0; j < 64; j += 4) {
            za = fmaf(sp[j],     wp[j],     za);
            zb = fmaf(sp[j + 1], wp[j + 1], zb);
            zc = fmaf(sp[j + 2], wp[j + 2], zc);
            zd = fmaf(sp[j + 3], wp[j + 3], zd);
        }
        z2[i] = (za + zb) + (zc + zd);
    }
    __syncthreads();

    if (tid < 11) {
        float v2 = 0.f;
#pragma unroll 8
        for (int t = 0; t < NT; t++) {
            float vv2 = v2 + z2[t * 11 + tid];
            float s2  = (vv2 >= 1.0f) ? 1.0f : 0.0f;
            vv2 = (s2 != 0.f) ? 0.f : vv2;
            v2 = fmaxf(vv2, -1.0f);
            out[(b * NT + t) * 11 + tid] = s2;
        }
    }
}

// ---------------------------------------------------------------------------
extern "C" void kernel_launch(void* const* d_in, const int* in_sizes, int n_in,
                              void* d_out, int out_size) {
    (void)in_sizes; (void)n_in; (void)out_size;
    const float* x  = (const float*)d_in[0];
    const float* w1 = (const float*)d_in[1];
    const float* w2 = (const float*)d_in[2];
    const float* w3 = (const float*)d_in[3];
    const float* w4 = (const float*)d_in[4];
    float* out = (float*)d_out;

    const int kc1Bytes = KC1_SMEM_FLOATS * 4;   // ~49.7 KB (dynamic)
    cudaFuncSetAttribute(kC1, cudaFuncAttributeMaxDynamicSharedMemorySize, kc1Bytes);

    // kA: normal launch
    kA<<<dim3(16, 25), 256>>>(x, w1);

    // kB / kC1 / kC2: programmatic dependent launches (overlap preamble with
    // predecessor tail; cudaGridDependencySynchronize guards the data dep)
    cudaLaunchAttribute pdlAttr[1];
    pdlAttr[0].id = cudaLaunchAttributeProgrammaticStreamSerialization;
    pdlAttr[0].val.programmaticStreamSerializationAllowed = 1;

    {
        cudaLaunchConfig_t cfg = {};
        cfg.gridDim = dim3(8, 2, 25);
        cfg.blockDim = dim3(64, 1, 1);
        cfg.attrs = pdlAttr;
        cfg.numAttrs = 1;
        cudaLaunchKernelEx(&cfg, kB, w2);
    }
    {
        cudaLaunchConfig_t cfg = {};
        cfg.gridDim = dim3(32, 4, 1);
        cfg.blockDim = dim3(256, 1, 1);
        cfg.dynamicSmemBytes = kc1Bytes;
        cfg.attrs = pdlAttr;
        cfg.numAttrs = 1;
        cudaLaunchKernelEx(&cfg, kC1, w3);
    }
    {
        cudaLaunchConfig_t cfg = {};
        cfg.gridDim = dim3(25, 1, 1);
        cfg.blockDim = dim3(256, 1, 1);
        cfg.attrs = pdlAttr;
        cfg.numAttrs = 1;
        cudaLaunchKernelEx(&cfg, kC2, w4, out);
    }
}